// round 2
// baseline (speedup 1.0000x reference)
#include <cuda_runtime.h>
#include <cuda_bf16.h>
#include <math.h>

// Zero-fill the output matrix with wide stores. out_size (64M) is a multiple
// of 4, so float4 stores are always in-bounds.
__global__ void zero_fill_kernel(float4* __restrict__ out, long long n_vec4) {
    long long i = (long long)blockIdx.x * blockDim.x + threadIdx.x;
    if (i < n_vec4) {
        out[i] = make_float4(0.f, 0.f, 0.f, 0.f);
    }
}

// One thread per (src,dst) pair: out[src*n + dst] = (len>0) ? b[min(len,maxpd)-1] : 0
__global__ void scatter_kernel(const int* __restrict__ path_src,
                               const int* __restrict__ path_dst,
                               const int* __restrict__ path_len,
                               const float* __restrict__ b,
                               float* __restrict__ out,
                               int P, long long n, int maxpd) {
    int i = blockIdx.x * blockDim.x + threadIdx.x;
    if (i >= P) return;
    int len = path_len[i];
    float v = 0.0f;
    if (len > 0) {
        int idx = (len < maxpd ? len : maxpd) - 1;
        if (idx < 0) idx = 0;
        if (idx > maxpd - 1) idx = maxpd - 1;
        v = __ldg(&b[idx]);
    }
    long long flat = (long long)path_src[i] * n + (long long)path_dst[i];
    out[flat] = v;
}

extern "C" void kernel_launch(void* const* d_in, const int* in_sizes, int n_in,
                              void* d_out, int out_size) {
    // metadata order: x (float32, N*D), b (float32, MAX_PATH),
    //                 path_src (int32, P), path_dst (int32, P), path_len (int32, P)
    const float* b        = (const float*)d_in[1];
    const int*   path_src = (const int*)d_in[2];
    const int*   path_dst = (const int*)d_in[3];
    const int*   path_len = (const int*)d_in[4];
    float* out = (float*)d_out;

    const int maxpd = in_sizes[1];
    const int P     = in_sizes[2];

    // out is n x n
    long long total = (long long)out_size;
    long long n = (long long)llround(sqrt((double)total));

    // 1) zero the output (256 MB) with float4 stores
    long long n_vec4 = total / 4;
    int threads = 256;
    long long blocks_ll = (n_vec4 + threads - 1) / threads;
    zero_fill_kernel<<<(unsigned int)blocks_ll, threads>>>((float4*)out, n_vec4);

    // 2) scatter the path values
    int sblocks = (P + threads - 1) / threads;
    scatter_kernel<<<sblocks, threads>>>(path_src, path_dst, path_len, b, out,
                                         P, n, maxpd);
}